// round 13
// baseline (speedup 1.0000x reference)
#include <cuda_runtime.h>
#include <cuda_fp16.h>

#define NN   50000
#define NE   800000
#define KIN  256
#define MOUT 128
#define NH   4

#define BMT 128
#define BKT 32
#define XPAD 36
#define GEMM_BLOCKS ((NN + BMT - 1) / BMT)      // 391
#define HIST_BLOCKS ((NE + 1023) / 1024)        // 782
#define CAPB 96                                  // bucket capacity per node
#define MAXOVF 4096

// Scratch (allocation-free rule: __device__ globals)
__device__ __align__(16) __half g_Wx_h[NN * MOUT];  // 12.8 MB fp16 Wx for agg
__device__ __align__(16) float g_ssrc[NN * NH];
__device__ __align__(16) float g_sdst[NN * NH];
__device__ int g_cnt[NN];          // zero-init; re-zeroed per replay by agg
__device__ int g_bucket[NN * CAPB];// 19.2 MB: src ids bucketed by dst
__device__ int g_ovf_src[MAXOVF];
__device__ int g_ovf_dst[MAXOVF];
__device__ int g_novf;             // overflow count (0 in practice)
__device__ int g_done;             // last-block ticket for agg

// ---------------------------------------------------------------------------
// Fused GEMM + bucketing-histogram kernel.
// Blocks [0, GEMM_BLOCKS): tf32 mma GEMM Wx = x@W^T + fused score epilogue.
// Blocks [GEMM_BLOCKS, +HIST_BLOCKS): per-dst count AND direct bucket write
//   (the atomic return IS the slot) — no scan, no fill needed afterwards.
// ---------------------------------------------------------------------------
__device__ __forceinline__ unsigned f2tf32(float f) {
    unsigned u;
    asm("cvt.rna.tf32.f32 %0, %1;" : "=r"(u) : "f"(f));
    return u;
}

__device__ __forceinline__ void mma_tf32(float* c, const unsigned* a,
                                         unsigned b0, unsigned b1) {
    asm volatile(
        "mma.sync.aligned.m16n8k8.row.col.f32.tf32.tf32.f32 "
        "{%0,%1,%2,%3}, {%4,%5,%6,%7}, {%8,%9}, {%0,%1,%2,%3};"
        : "+f"(c[0]), "+f"(c[1]), "+f"(c[2]), "+f"(c[3])
        : "r"(a[0]), "r"(a[1]), "r"(a[2]), "r"(a[3]), "r"(b0), "r"(b1));
}

__global__ __launch_bounds__(256, 2)
void gemm_hist_kernel(const float* __restrict__ x,
                      const float* __restrict__ W,
                      const float* __restrict__ aw,
                      const int* __restrict__ ei) {
    __shared__ unsigned Xs[BMT * XPAD];
    __shared__ unsigned Ws[MOUT * XPAD];

    if (blockIdx.x >= GEMM_BLOCKS) {
        // ---- bucketing histogram branch ----
        int base = (blockIdx.x - GEMM_BLOCKS) * 1024 + threadIdx.x;
        #pragma unroll
        for (int j = 0; j < 4; j++) {
            int e = base + j * 256;
            if (e < NE) {
                int s = ei[e];
                int d = ei[NE + e];
                int lp = atomicAdd(&g_cnt[d], 1);
                if (lp < CAPB) {
                    g_bucket[d * CAPB + lp] = s;
                } else {
                    int o = atomicAdd(&g_novf, 1);
                    if (o < MAXOVF) { g_ovf_src[o] = s; g_ovf_dst[o] = d; }
                }
            }
        }
        return;
    }

    // ---- GEMM branch (unchanged) ----
    int tid  = threadIdx.x;
    int lane = tid & 31;
    int warp = tid >> 5;
    int g = lane >> 2;
    int t = lane & 3;
    int wm = warp & 3;
    int wn = warp >> 2;
    int row0 = blockIdx.x * BMT;

    float c[2][8][4];
    #pragma unroll
    for (int tm = 0; tm < 2; tm++)
        #pragma unroll
        for (int tn = 0; tn < 8; tn++)
            #pragma unroll
            for (int i = 0; i < 4; i++) c[tm][tn][i] = 0.f;

    for (int k0 = 0; k0 < KIN; k0 += BKT) {
        #pragma unroll
        for (int j = 0; j < 4; j++) {
            int idx = tid + 256 * j;
            int m   = idx >> 3;
            int kv  = (idx & 7) * 4;
            int row = row0 + m;
            float4 v = make_float4(0.f, 0.f, 0.f, 0.f);
            if (row < NN) v = *(const float4*)&x[row * KIN + k0 + kv];
            uint4 u;
            u.x = f2tf32(v.x); u.y = f2tf32(v.y);
            u.z = f2tf32(v.z); u.w = f2tf32(v.w);
            *(uint4*)&Xs[m * XPAD + kv] = u;

            float4 w4 = *(const float4*)&W[m * KIN + k0 + kv];
            uint4 uw;
            uw.x = f2tf32(w4.x); uw.y = f2tf32(w4.y);
            uw.z = f2tf32(w4.z); uw.w = f2tf32(w4.w);
            *(uint4*)&Ws[m * XPAD + kv] = uw;
        }
        __syncthreads();

        #pragma unroll
        for (int kk = 0; kk < BKT; kk += 8) {
            unsigned a[2][4];
            #pragma unroll
            for (int tm = 0; tm < 2; tm++) {
                int r = wm * 32 + tm * 16 + g;
                a[tm][0] = Xs[r * XPAD + kk + t];
                a[tm][1] = Xs[(r + 8) * XPAD + kk + t];
                a[tm][2] = Xs[r * XPAD + kk + t + 4];
                a[tm][3] = Xs[(r + 8) * XPAD + kk + t + 4];
            }
            #pragma unroll
            for (int tn = 0; tn < 8; tn++) {
                int n = wn * 64 + tn * 8 + g;
                unsigned b0 = Ws[n * XPAD + kk + t];
                unsigned b1 = Ws[n * XPAD + kk + t + 4];
                mma_tf32(c[0][tn], a[0], b0, b1);
                mma_tf32(c[1][tn], a[1], b0, b1);
            }
        }
        __syncthreads();
    }

    float as_r[4][2], ad_r[4][2];
    #pragma unroll
    for (int q = 0; q < 4; q++)
        #pragma unroll
        for (int j = 0; j < 2; j++) {
            as_r[q][j] = aw[q * 8 + 2 * t + j];
            ad_r[q][j] = aw[32 + q * 8 + 2 * t + j];
        }

    #pragma unroll
    for (int tm = 0; tm < 2; tm++)
    #pragma unroll
    for (int half = 0; half < 2; half++) {
        int row = row0 + wm * 32 + tm * 16 + half * 8 + g;

        if (row < NN) {
            #pragma unroll
            for (int tn = 0; tn < 8; tn++) {
                __half2 hv = __floats2half2_rn(c[tm][tn][half * 2],
                                               c[tm][tn][half * 2 + 1]);
                *(__half2*)&g_Wx_h[row * MOUT + wn * 64 + tn * 8 + 2 * t] = hv;
            }
        }

        #pragma unroll
        for (int hl = 0; hl < 2; hl++) {
            float ps = 0.f, pd = 0.f;
            #pragma unroll
            for (int q = 0; q < 4; q++)
                #pragma unroll
                for (int j = 0; j < 2; j++) {
                    float v = c[tm][hl * 4 + q][half * 2 + j];
                    ps += v * as_r[q][j];
                    pd += v * ad_r[q][j];
                }
            ps += __shfl_xor_sync(0xffffffffu, ps, 1);
            ps += __shfl_xor_sync(0xffffffffu, ps, 2);
            pd += __shfl_xor_sync(0xffffffffu, pd, 1);
            pd += __shfl_xor_sync(0xffffffffu, pd, 2);
            if (t == 0 && row < NN) {
                g_ssrc[row * NH + wn * 2 + hl] = ps;
                g_sdst[row * NH + wn * 2 + hl] = pd;
            }
        }
    }
}

// ---------------------------------------------------------------------------
// Aggregation: warp per dst node, two-pass, smem numerator cache, bucket
// gather. Re-zeroes g_cnt (same warp that read it) + g_novf (last block).
// ---------------------------------------------------------------------------
#define CAP 64

__device__ __forceinline__ float lrelu_exp(float v) {
    float r = v > 0.f ? v : 0.2f * v;
    return __expf(r);
}

__global__ __launch_bounds__(256)
void agg_kernel(float* __restrict__ out) {
    __shared__ float s_al[8][CAP][NH];   // 8 KB per block

    int w = threadIdx.x >> 5;
    int d = blockIdx.x * 8 + w;          // NN divisible by 8*625? 6250*8=50000 exact
    int lane = threadIdx.x & 31;

    if (d < NN) {
        int cnt = g_cnt[d];
        if (lane == 0) g_cnt[d] = 0;     // replay invariant (after read, same warp)
        int deg = cnt < CAPB ? cnt : CAPB;
        int beg = d * CAPB;

        float4 sd4 = *(const float4*)&g_sdst[d * 4];

        // Pass 1: per-edge numerators -> smem + denom reduction
        float4 dn = make_float4(0.f, 0.f, 0.f, 0.f);
        for (int j = lane; j < deg; j += 32) {
            int s = g_bucket[beg + j];
            float4 a = *(const float4*)&g_ssrc[s * 4];
            float4 e;
            e.x = lrelu_exp(a.x + sd4.x);
            e.y = lrelu_exp(a.y + sd4.y);
            e.z = lrelu_exp(a.z + sd4.z);
            e.w = lrelu_exp(a.w + sd4.w);
            dn.x += e.x; dn.y += e.y; dn.z += e.z; dn.w += e.w;
            if (j < CAP) *(float4*)&s_al[w][j][0] = e;
        }
        // overflow contributions (cnt > CAPB never happens in practice)
        if (cnt > CAPB && lane == 0) {
            int novf = g_novf;
            for (int o = 0; o < novf && o < MAXOVF; o++) {
                if (g_ovf_dst[o] == d) {
                    int s = g_ovf_src[o];
                    float4 a = *(const float4*)&g_ssrc[s * 4];
                    dn.x += lrelu_exp(a.x + sd4.x);
                    dn.y += lrelu_exp(a.y + sd4.y);
                    dn.z += lrelu_exp(a.z + sd4.z);
                    dn.w += lrelu_exp(a.w + sd4.w);
                }
            }
        }
        #pragma unroll
        for (int m = 16; m; m >>= 1) {
            dn.x += __shfl_xor_sync(0xffffffffu, dn.x, m);
            dn.y += __shfl_xor_sync(0xffffffffu, dn.y, m);
            dn.z += __shfl_xor_sync(0xffffffffu, dn.z, m);
            dn.w += __shfl_xor_sync(0xffffffffu, dn.w, m);
        }
        __syncwarp();

        int h = lane >> 3;
        float dnh = (h == 0) ? dn.x : (h == 1) ? dn.y : (h == 2) ? dn.z : dn.w;
        float adh = (h == 0) ? sd4.x : (h == 1) ? sd4.y : (h == 2) ? sd4.z : sd4.w;
        float invd = __fdividef(1.f, dnh + 1e-8f);

        // Pass 2: weighted fp16 gather
        float4 acc = make_float4(0.f, 0.f, 0.f, 0.f);
        if (deg <= CAP) {
            const float* al_base = &s_al[w][0][h];
            #pragma unroll 4
            for (int j = 0; j < deg; j++) {
                float al = al_base[j * NH] * invd;
                int s = g_bucket[beg + j];
                float2 raw = *(const float2*)&g_Wx_h[s * MOUT + lane * 4];
                __half2 h01 = ((__half2*)&raw)[0];
                __half2 h23 = ((__half2*)&raw)[1];
                float2 f01 = __half22float2(h01);
                float2 f23 = __half22float2(h23);
                acc.x += al * f01.x; acc.y += al * f01.y;
                acc.z += al * f23.x; acc.w += al * f23.y;
            }
        } else {
            #pragma unroll 2
            for (int j = 0; j < deg; j++) {
                int s = g_bucket[beg + j];
                float al = lrelu_exp(g_ssrc[s * 4 + h] + adh) * invd;
                float2 raw = *(const float2*)&g_Wx_h[s * MOUT + lane * 4];
                __half2 h01 = ((__half2*)&raw)[0];
                __half2 h23 = ((__half2*)&raw)[1];
                float2 f01 = __half22float2(h01);
                float2 f23 = __half22float2(h23);
                acc.x += al * f01.x; acc.y += al * f01.y;
                acc.z += al * f23.x; acc.w += al * f23.y;
            }
            int novf = g_novf;
            for (int o = 0; o < novf && o < MAXOVF; o++) {
                if (g_ovf_dst[o] == d) {
                    int s = g_ovf_src[o];
                    float al = lrelu_exp(g_ssrc[s * 4 + h] + adh) * invd;
                    float2 raw = *(const float2*)&g_Wx_h[s * MOUT + lane * 4];
                    __half2 h01 = ((__half2*)&raw)[0];
                    __half2 h23 = ((__half2*)&raw)[1];
                    float2 f01 = __half22float2(h01);
                    float2 f23 = __half22float2(h23);
                    acc.x += al * f01.x; acc.y += al * f01.y;
                    acc.z += al * f23.x; acc.w += al * f23.y;
                }
            }
        }

        acc.x = acc.x > 0.f ? acc.x : expm1f(acc.x);
        acc.y = acc.y > 0.f ? acc.y : expm1f(acc.y);
        acc.z = acc.z > 0.f ? acc.z : expm1f(acc.z);
        acc.w = acc.w > 0.f ? acc.w : expm1f(acc.w);
        *(float4*)&out[d * MOUT + lane * 4] = acc;
    }

    // last-block ticket: reset overflow counter for next replay
    __syncthreads();
    if (threadIdx.x == 0) {
        int old = atomicAdd(&g_done, 1);
        if (old == (int)gridDim.x - 1) { g_done = 0; g_novf = 0; }
    }
}

// ---------------------------------------------------------------------------
extern "C" void kernel_launch(void* const* d_in, const int* in_sizes, int n_in,
                              void* d_out, int out_size) {
    const float* x  = (const float*)d_in[0];
    const int*   ei = (const int*)d_in[1];
    const float* W  = (const float*)d_in[2];
    const float* aw = (const float*)d_in[3];
    float* out = (float*)d_out;

    gemm_hist_kernel<<<GEMM_BLOCKS + HIST_BLOCKS, 256>>>(x, W, aw, ei);
    agg_kernel<<<NN / 8, 256>>>(out);
}

// round 14
// speedup vs baseline: 1.5154x; 1.5154x over previous
#include <cuda_runtime.h>
#include <cuda_fp16.h>

#define NN   50000
#define NE   800000
#define KIN  256
#define MOUT 128
#define NH   4
#define NB   196        // ceil(NN/256)

#define BMT 128
#define BKT 32
#define XPAD 36
#define GEMM_BLOCKS ((NN + BMT - 1) / BMT)      // 391
#define HIST_BLOCKS ((NE + 1023) / 1024)        // 782

// Scratch (allocation-free rule: __device__ globals)
__device__ __align__(16) __half g_Wx_h[NN * MOUT];  // 12.8 MB fp16 Wx for agg
__device__ __align__(16) float g_ssrc[NN * NH];
__device__ __align__(16) float g_sdst[NN * NH];
__device__ int g_cnt[NN];     // zero-init at load; re-zeroed by agg each replay
__device__ int g_scan[NN];
__device__ int g_bsum[NB];
__device__ int g_off[NN + 1];
__device__ int g_lpos[NE];    // per-edge position within its dst segment
__device__ int g_esrc[NE];

// ---------------------------------------------------------------------------
// Fused GEMM + histogram kernel (identical to round 12).
// ---------------------------------------------------------------------------
__device__ __forceinline__ unsigned f2tf32(float f) {
    unsigned u;
    asm("cvt.rna.tf32.f32 %0, %1;" : "=r"(u) : "f"(f));
    return u;
}

__device__ __forceinline__ void mma_tf32(float* c, const unsigned* a,
                                         unsigned b0, unsigned b1) {
    asm volatile(
        "mma.sync.aligned.m16n8k8.row.col.f32.tf32.tf32.f32 "
        "{%0,%1,%2,%3}, {%4,%5,%6,%7}, {%8,%9}, {%0,%1,%2,%3};"
        : "+f"(c[0]), "+f"(c[1]), "+f"(c[2]), "+f"(c[3])
        : "r"(a[0]), "r"(a[1]), "r"(a[2]), "r"(a[3]), "r"(b0), "r"(b1));
}

__global__ __launch_bounds__(256, 2)
void gemm_hist_kernel(const float* __restrict__ x,
                      const float* __restrict__ W,
                      const float* __restrict__ aw,
                      const int* __restrict__ ei) {
    __shared__ unsigned Xs[BMT * XPAD];
    __shared__ unsigned Ws[MOUT * XPAD];

    if (blockIdx.x >= GEMM_BLOCKS) {
        int base = (blockIdx.x - GEMM_BLOCKS) * 1024 + threadIdx.x;
        #pragma unroll
        for (int j = 0; j < 4; j++) {
            int e = base + j * 256;
            if (e < NE) {
                int d = ei[NE + e];
                int lp = atomicAdd(&g_cnt[d], 1);
                g_lpos[e] = lp;
            }
        }
        return;
    }

    int tid  = threadIdx.x;
    int lane = tid & 31;
    int warp = tid >> 5;
    int g = lane >> 2;
    int t = lane & 3;
    int wm = warp & 3;
    int wn = warp >> 2;
    int row0 = blockIdx.x * BMT;

    float c[2][8][4];
    #pragma unroll
    for (int tm = 0; tm < 2; tm++)
        #pragma unroll
        for (int tn = 0; tn < 8; tn++)
            #pragma unroll
            for (int i = 0; i < 4; i++) c[tm][tn][i] = 0.f;

    for (int k0 = 0; k0 < KIN; k0 += BKT) {
        #pragma unroll
        for (int j = 0; j < 4; j++) {
            int idx = tid + 256 * j;
            int m   = idx >> 3;
            int kv  = (idx & 7) * 4;
            int row = row0 + m;
            float4 v = make_float4(0.f, 0.f, 0.f, 0.f);
            if (row < NN) v = *(const float4*)&x[row * KIN + k0 + kv];
            uint4 u;
            u.x = f2tf32(v.x); u.y = f2tf32(v.y);
            u.z = f2tf32(v.z); u.w = f2tf32(v.w);
            *(uint4*)&Xs[m * XPAD + kv] = u;

            float4 w4 = *(const float4*)&W[m * KIN + k0 + kv];
            uint4 uw;
            uw.x = f2tf32(w4.x); uw.y = f2tf32(w4.y);
            uw.z = f2tf32(w4.z); uw.w = f2tf32(w4.w);
            *(uint4*)&Ws[m * XPAD + kv] = uw;
        }
        __syncthreads();

        #pragma unroll
        for (int kk = 0; kk < BKT; kk += 8) {
            unsigned a[2][4];
            #pragma unroll
            for (int tm = 0; tm < 2; tm++) {
                int r = wm * 32 + tm * 16 + g;
                a[tm][0] = Xs[r * XPAD + kk + t];
                a[tm][1] = Xs[(r + 8) * XPAD + kk + t];
                a[tm][2] = Xs[r * XPAD + kk + t + 4];
                a[tm][3] = Xs[(r + 8) * XPAD + kk + t + 4];
            }
            #pragma unroll
            for (int tn = 0; tn < 8; tn++) {
                int n = wn * 64 + tn * 8 + g;
                unsigned b0 = Ws[n * XPAD + kk + t];
                unsigned b1 = Ws[n * XPAD + kk + t + 4];
                mma_tf32(c[0][tn], a[0], b0, b1);
                mma_tf32(c[1][tn], a[1], b0, b1);
            }
        }
        __syncthreads();
    }

    float as_r[4][2], ad_r[4][2];
    #pragma unroll
    for (int q = 0; q < 4; q++)
        #pragma unroll
        for (int j = 0; j < 2; j++) {
            as_r[q][j] = aw[q * 8 + 2 * t + j];
            ad_r[q][j] = aw[32 + q * 8 + 2 * t + j];
        }

    #pragma unroll
    for (int tm = 0; tm < 2; tm++)
    #pragma unroll
    for (int half = 0; half < 2; half++) {
        int row = row0 + wm * 32 + tm * 16 + half * 8 + g;

        if (row < NN) {
            #pragma unroll
            for (int tn = 0; tn < 8; tn++) {
                __half2 hv = __floats2half2_rn(c[tm][tn][half * 2],
                                               c[tm][tn][half * 2 + 1]);
                *(__half2*)&g_Wx_h[row * MOUT + wn * 64 + tn * 8 + 2 * t] = hv;
            }
        }

        #pragma unroll
        for (int hl = 0; hl < 2; hl++) {
            float ps = 0.f, pd = 0.f;
            #pragma unroll
            for (int q = 0; q < 4; q++)
                #pragma unroll
                for (int j = 0; j < 2; j++) {
                    float v = c[tm][hl * 4 + q][half * 2 + j];
                    ps += v * as_r[q][j];
                    pd += v * ad_r[q][j];
                }
            ps += __shfl_xor_sync(0xffffffffu, ps, 1);
            ps += __shfl_xor_sync(0xffffffffu, ps, 2);
            pd += __shfl_xor_sync(0xffffffffu, pd, 1);
            pd += __shfl_xor_sync(0xffffffffu, pd, 2);
            if (t == 0 && row < NN) {
                g_ssrc[row * NH + wn * 2 + hl] = ps;
                g_sdst[row * NH + wn * 2 + hl] = pd;
            }
        }
    }
}

// ---------------------------------------------------------------------------
// Scan: per-block inclusive (coalesced) + redundant block-sum apply
// ---------------------------------------------------------------------------
__global__ void scan1_kernel() {
    __shared__ int sh[256];
    int t = threadIdx.x;
    int i = blockIdx.x * 256 + t;
    int v = (i < NN) ? g_cnt[i] : 0;
    sh[t] = v;
    __syncthreads();
    #pragma unroll
    for (int ofs = 1; ofs < 256; ofs <<= 1) {
        int add = (t >= ofs) ? sh[t - ofs] : 0;
        __syncthreads();
        sh[t] += add;
        __syncthreads();
    }
    if (i < NN) g_scan[i] = sh[t];
    if (t == 255) g_bsum[blockIdx.x] = sh[255];
}

__global__ void scan_apply_kernel() {
    __shared__ int sh[256];
    int t = threadIdx.x;
    sh[t] = (t < NB) ? g_bsum[t] : 0;
    __syncthreads();
    #pragma unroll
    for (int ofs = 1; ofs < 256; ofs <<= 1) {
        int add = (t >= ofs) ? sh[t - ofs] : 0;
        __syncthreads();
        sh[t] += add;
        __syncthreads();
    }
    int base = (blockIdx.x == 0) ? 0 : sh[blockIdx.x - 1];
    int i = blockIdx.x * 256 + t;
    if (i < NN) g_off[i] = g_scan[i] - g_cnt[i] + base;
    if (i == 0) g_off[NN] = NE;
}

// Atomic-free fill, 8 edges/thread.
__global__ void fill_kernel(const int* __restrict__ ei) {
    int b = (blockIdx.x * blockDim.x + threadIdx.x) * 8;
    if (b >= NE) return;
    int n = (NE - b < 8) ? (NE - b) : 8;
    int s[8], d[8], lp[8];
    #pragma unroll
    for (int j = 0; j < 8; j++) {
        if (j < n) {
            s[j]  = ei[b + j];
            d[j]  = ei[NE + b + j];
            lp[j] = g_lpos[b + j];
        }
    }
    #pragma unroll
    for (int j = 0; j < 8; j++)
        if (j < n) g_esrc[g_off[d[j]] + lp[j]] = s[j];
}

// ---------------------------------------------------------------------------
// Aggregation: warp per TWO consecutive dst nodes, two-pass, smem numerator
// cache, interleaved pass-2 (2 independent chains per iteration, warp-uniform
// guards). Re-zeroes g_cnt for next replay.
// ---------------------------------------------------------------------------
#define CAP 64

__device__ __forceinline__ float lrelu_exp(float v) {
    float r = v > 0.f ? v : 0.2f * v;
    return __expf(r);
}

__global__ __launch_bounds__(256)
void agg_kernel(float* __restrict__ out) {
    __shared__ float s_al[8][2][CAP][NH];   // 16 KB per block

    // re-zero count array for the next replay (all consumers done)
    int gid = blockIdx.x * blockDim.x + threadIdx.x;
    if (gid < NN) g_cnt[gid] = 0;

    int w = threadIdx.x >> 5;
    int lane = threadIdx.x & 31;
    int d0 = blockIdx.x * 16 + w * 2;       // 3125*16 = 50000 exact
    int d1 = d0 + 1;

    int off0 = g_off[d0];
    int off1 = g_off[d1];
    int off2 = g_off[d1 + 1];
    int deg0 = off1 - off0;
    int deg1 = off2 - off1;

    float4 sa4 = *(const float4*)&g_sdst[d0 * 4];
    float4 sb4 = *(const float4*)&g_sdst[d1 * 4];

    // Pass 1: numerators -> smem + denom reductions (two nodes)
    float4 dn0 = make_float4(0.f, 0.f, 0.f, 0.f);
    float4 dn1 = make_float4(0.f, 0.f, 0.f, 0.f);
    for (int j = lane; j < deg0; j += 32) {
        int s = g_esrc[off0 + j];
        float4 a = *(const float4*)&g_ssrc[s * 4];
        float4 e;
        e.x = lrelu_exp(a.x + sa4.x);
        e.y = lrelu_exp(a.y + sa4.y);
        e.z = lrelu_exp(a.z + sa4.z);
        e.w = lrelu_exp(a.w + sa4.w);
        dn0.x += e.x; dn0.y += e.y; dn0.z += e.z; dn0.w += e.w;
        if (j < CAP) *(float4*)&s_al[w][0][j][0] = e;
    }
    for (int j = lane; j < deg1; j += 32) {
        int s = g_esrc[off1 + j];
        float4 a = *(const float4*)&g_ssrc[s * 4];
        float4 e;
        e.x = lrelu_exp(a.x + sb4.x);
        e.y = lrelu_exp(a.y + sb4.y);
        e.z = lrelu_exp(a.z + sb4.z);
        e.w = lrelu_exp(a.w + sb4.w);
        dn1.x += e.x; dn1.y += e.y; dn1.z += e.z; dn1.w += e.w;
        if (j < CAP) *(float4*)&s_al[w][1][j][0] = e;
    }
    #pragma unroll
    for (int m = 16; m; m >>= 1) {
        dn0.x += __shfl_xor_sync(0xffffffffu, dn0.x, m);
        dn0.y += __shfl_xor_sync(0xffffffffu, dn0.y, m);
        dn0.z += __shfl_xor_sync(0xffffffffu, dn0.z, m);
        dn0.w += __shfl_xor_sync(0xffffffffu, dn0.w, m);
        dn1.x += __shfl_xor_sync(0xffffffffu, dn1.x, m);
        dn1.y += __shfl_xor_sync(0xffffffffu, dn1.y, m);
        dn1.z += __shfl_xor_sync(0xffffffffu, dn1.z, m);
        dn1.w += __shfl_xor_sync(0xffffffffu, dn1.w, m);
    }
    __syncwarp();

    int h = lane >> 3;
    float dnh0 = (h == 0) ? dn0.x : (h == 1) ? dn0.y : (h == 2) ? dn0.z : dn0.w;
    float dnh1 = (h == 0) ? dn1.x : (h == 1) ? dn1.y : (h == 2) ? dn1.z : dn1.w;
    float ad0 = (h == 0) ? sa4.x : (h == 1) ? sa4.y : (h == 2) ? sa4.z : sa4.w;
    float ad1 = (h == 0) ? sb4.x : (h == 1) ? sb4.y : (h == 2) ? sb4.z : sb4.w;
    float invd0 = __fdividef(1.f, dnh0 + 1e-8f);
    float invd1 = __fdividef(1.f, dnh1 + 1e-8f);

    float4 acc0 = make_float4(0.f, 0.f, 0.f, 0.f);
    float4 acc1 = make_float4(0.f, 0.f, 0.f, 0.f);

    if (deg0 <= CAP && deg1 <= CAP) {
        // interleaved fast loop: 2 independent chains, warp-uniform guards
        const float* alb0 = &s_al[w][0][0][h];
        const float* alb1 = &s_al[w][1][0][h];
        int mx = deg0 > deg1 ? deg0 : deg1;
        #pragma unroll 2
        for (int j = 0; j < mx; j++) {
            if (j < deg0) {
                float al = alb0[j * NH] * invd0;
                int s = g_esrc[off0 + j];
                float2 raw = *(const float2*)&g_Wx_h[s * MOUT + lane * 4];
                __half2 h01 = ((__half2*)&raw)[0];
                __half2 h23 = ((__half2*)&raw)[1];
                float2 f01 = __half22float2(h01);
                float2 f23 = __half22float2(h23);
                acc0.x += al * f01.x; acc0.y += al * f01.y;
                acc0.z += al * f23.x; acc0.w += al * f23.y;
            }
            if (j < deg1) {
                float al = alb1[j * NH] * invd1;
                int s = g_esrc[off1 + j];
                float2 raw = *(const float2*)&g_Wx_h[s * MOUT + lane * 4];
                __half2 h01 = ((__half2*)&raw)[0];
                __half2 h23 = ((__half2*)&raw)[1];
                float2 f01 = __half22float2(h01);
                float2 f23 = __half22float2(h23);
                acc1.x += al * f01.x; acc1.y += al * f01.y;
                acc1.z += al * f23.x; acc1.w += al * f23.y;
            }
        }
    } else {
        // safe fallback: recompute numerators (essentially never taken)
        for (int j = 0; j < deg0; j++) {
            int s = g_esrc[off0 + j];
            float al = lrelu_exp(g_ssrc[s * 4 + h] + ad0) * invd0;
            float2 raw = *(const float2*)&g_Wx_h[s * MOUT + lane * 4];
            __half2 h01 = ((__half2*)&raw)[0];
            __half2 h23 = ((__half2*)&raw)[1];
            float2 f01 = __half22float2(h01);
            float2 f23 = __half22float2(h23);
            acc0.x += al * f01.x; acc0.y += al * f01.y;
            acc0.z += al * f23.x; acc0.w += al * f23.y;
        }
        for (int j = 0; j < deg1; j++) {
            int s = g_esrc[off1 + j];
            float al = lrelu_exp(g_ssrc[s * 4 + h] + ad1) * invd1;
            float2 raw = *(const float2*)&g_Wx_h[s * MOUT + lane * 4];
            __half2 h01 = ((__half2*)&raw)[0];
            __half2 h23 = ((__half2*)&raw)[1];
            float2 f01 = __half22float2(h01);
            float2 f23 = __half22float2(h23);
            acc1.x += al * f01.x; acc1.y += al * f01.y;
            acc1.z += al * f23.x; acc1.w += al * f23.y;
        }
    }

    acc0.x = acc0.x > 0.f ? acc0.x : expm1f(acc0.x);
    acc0.y = acc0.y > 0.f ? acc0.y : expm1f(acc0.y);
    acc0.z = acc0.z > 0.f ? acc0.z : expm1f(acc0.z);
    acc0.w = acc0.w > 0.f ? acc0.w : expm1f(acc0.w);
    acc1.x = acc1.x > 0.f ? acc1.x : expm1f(acc1.x);
    acc1.y = acc1.y > 0.f ? acc1.y : expm1f(acc1.y);
    acc1.z = acc1.z > 0.f ? acc1.z : expm1f(acc1.z);
    acc1.w = acc1.w > 0.f ? acc1.w : expm1f(acc1.w);
    *(float4*)&out[d0 * MOUT + lane * 4] = acc0;
    *(float4*)&out[d1 * MOUT + lane * 4] = acc1;
}

// ---------------------------------------------------------------------------
extern "C" void kernel_launch(void* const* d_in, const int* in_sizes, int n_in,
                              void* d_out, int out_size) {
    const float* x  = (const float*)d_in[0];
    const int*   ei = (const int*)d_in[1];
    const float* W  = (const float*)d_in[2];
    const float* aw = (const float*)d_in[3];
    float* out = (float*)d_out;

    gemm_hist_kernel<<<GEMM_BLOCKS + HIST_BLOCKS, 256>>>(x, W, aw, ei);
    scan1_kernel<<<NB, 256>>>();
    scan_apply_kernel<<<NB, 256>>>();
    fill_kernel<<<(NE / 8 + 255) / 256, 256>>>(ei);
    agg_kernel<<<NN / 16, 256>>>(out);
}

// round 15
// speedup vs baseline: 1.8076x; 1.1928x over previous
#include <cuda_runtime.h>
#include <cuda_fp16.h>

#define NN   50000
#define NE   800000
#define KIN  256
#define MOUT 128
#define NH   4
#define NB   196        // ceil(NN/256)

#define BMT 128
#define BKT 32
#define XPADH 40        // row stride in halves (80B): conflict-free fragments
#define GEMM_BLOCKS ((NN + BMT - 1) / BMT)      // 391
#define HIST_BLOCKS ((NE + 1023) / 1024)        // 782

// Scratch (allocation-free rule: __device__ globals)
__device__ __align__(16) __half g_Wx_h[NN * MOUT];  // 12.8 MB fp16 Wx for agg
__device__ __align__(16) float g_ssrc[NN * NH];
__device__ __align__(16) float g_sdst[NN * NH];
__device__ int g_cnt[NN];     // zero-init at load; re-zeroed by agg each replay
__device__ int g_scan[NN];
__device__ int g_bsum[NB];
__device__ int g_off[NN + 1];
__device__ int g_lpos[NE];    // per-edge position within its dst segment
__device__ int g_esrc[NE];

// ---------------------------------------------------------------------------
// Fused GEMM + histogram kernel. GEMM now fp16 mma.m16n8k16 (fp32 accum).
// Blocks [0, GEMM_BLOCKS): GEMM Wx = x@W^T + fused score epilogue.
// Blocks [GEMM_BLOCKS, +HIST_BLOCKS): per-dst histogram recording lpos.
// ---------------------------------------------------------------------------
__device__ __forceinline__ void mma_fp16(float* c, const unsigned* a,
                                         unsigned b0, unsigned b1) {
    asm volatile(
        "mma.sync.aligned.m16n8k16.row.col.f32.f16.f16.f32 "
        "{%0,%1,%2,%3}, {%4,%5,%6,%7}, {%8,%9}, {%0,%1,%2,%3};"
        : "+f"(c[0]), "+f"(c[1]), "+f"(c[2]), "+f"(c[3])
        : "r"(a[0]), "r"(a[1]), "r"(a[2]), "r"(a[3]), "r"(b0), "r"(b1));
}

__global__ __launch_bounds__(256, 2)
void gemm_hist_kernel(const float* __restrict__ x,
                      const float* __restrict__ W,
                      const float* __restrict__ aw,
                      const int* __restrict__ ei) {
    __shared__ __half Xs[BMT * XPADH];   // 10 KB
    __shared__ __half Ws[MOUT * XPADH];  // 10 KB

    if (blockIdx.x >= GEMM_BLOCKS) {
        // ---- histogram branch: count + record local position ----
        int base = (blockIdx.x - GEMM_BLOCKS) * 1024 + threadIdx.x;
        #pragma unroll
        for (int j = 0; j < 4; j++) {
            int e = base + j * 256;
            if (e < NE) {
                int d = ei[NE + e];
                int lp = atomicAdd(&g_cnt[d], 1);
                g_lpos[e] = lp;
            }
        }
        return;
    }

    // ---- GEMM branch ----
    int tid  = threadIdx.x;
    int lane = tid & 31;
    int warp = tid >> 5;
    int g = lane >> 2;
    int t = lane & 3;
    int wm = warp & 3;
    int wn = warp >> 2;
    int row0 = blockIdx.x * BMT;

    float c[2][8][4];
    #pragma unroll
    for (int tm = 0; tm < 2; tm++)
        #pragma unroll
        for (int tn = 0; tn < 8; tn++)
            #pragma unroll
            for (int i = 0; i < 4; i++) c[tm][tn][i] = 0.f;

    for (int k0 = 0; k0 < KIN; k0 += BKT) {
        // Stage X and W tiles (128x32), converted to fp16.
        #pragma unroll
        for (int j = 0; j < 4; j++) {
            int idx = tid + 256 * j;
            int m   = idx >> 3;
            int kv  = (idx & 7) * 4;
            int row = row0 + m;
            float4 v = make_float4(0.f, 0.f, 0.f, 0.f);
            if (row < NN) v = *(const float4*)&x[row * KIN + k0 + kv];
            __half2 hx0 = __floats2half2_rn(v.x, v.y);
            __half2 hx1 = __floats2half2_rn(v.z, v.w);
            uint2 ux = make_uint2(*(unsigned*)&hx0, *(unsigned*)&hx1);
            *(uint2*)&Xs[m * XPADH + kv] = ux;

            float4 w4 = *(const float4*)&W[m * KIN + k0 + kv];
            __half2 hw0 = __floats2half2_rn(w4.x, w4.y);
            __half2 hw1 = __floats2half2_rn(w4.z, w4.w);
            uint2 uw = make_uint2(*(unsigned*)&hw0, *(unsigned*)&hw1);
            *(uint2*)&Ws[m * XPADH + kv] = uw;
        }
        __syncthreads();

        #pragma unroll
        for (int kk = 0; kk < BKT; kk += 16) {
            unsigned a[2][4];
            #pragma unroll
            for (int tm = 0; tm < 2; tm++) {
                int r = wm * 32 + tm * 16 + g;
                a[tm][0] = *(unsigned*)&Xs[r * XPADH + kk + 2 * t];
                a[tm][1] = *(unsigned*)&Xs[(r + 8) * XPADH + kk + 2 * t];
                a[tm][2] = *(unsigned*)&Xs[r * XPADH + kk + 2 * t + 8];
                a[tm][3] = *(unsigned*)&Xs[(r + 8) * XPADH + kk + 2 * t + 8];
            }
            #pragma unroll
            for (int tn = 0; tn < 8; tn++) {
                int n = wn * 64 + tn * 8 + g;
                unsigned b0 = *(unsigned*)&Ws[n * XPADH + kk + 2 * t];
                unsigned b1 = *(unsigned*)&Ws[n * XPADH + kk + 2 * t + 8];
                mma_fp16(c[0][tn], a[0], b0, b1);
                mma_fp16(c[1][tn], a[1], b0, b1);
            }
        }
        __syncthreads();
    }

    // Epilogue (identical fragment layout to tf32 version)
    float as_r[4][2], ad_r[4][2];
    #pragma unroll
    for (int q = 0; q < 4; q++)
        #pragma unroll
        for (int j = 0; j < 2; j++) {
            as_r[q][j] = aw[q * 8 + 2 * t + j];
            ad_r[q][j] = aw[32 + q * 8 + 2 * t + j];
        }

    #pragma unroll
    for (int tm = 0; tm < 2; tm++)
    #pragma unroll
    for (int half = 0; half < 2; half++) {
        int row = row0 + wm * 32 + tm * 16 + half * 8 + g;

        if (row < NN) {
            #pragma unroll
            for (int tn = 0; tn < 8; tn++) {
                __half2 hv = __floats2half2_rn(c[tm][tn][half * 2],
                                               c[tm][tn][half * 2 + 1]);
                *(__half2*)&g_Wx_h[row * MOUT + wn * 64 + tn * 8 + 2 * t] = hv;
            }
        }

        #pragma unroll
        for (int hl = 0; hl < 2; hl++) {
            float ps = 0.f, pd = 0.f;
            #pragma unroll
            for (int q = 0; q < 4; q++)
                #pragma unroll
                for (int j = 0; j < 2; j++) {
                    float v = c[tm][hl * 4 + q][half * 2 + j];
                    ps += v * as_r[q][j];
                    pd += v * ad_r[q][j];
                }
            ps += __shfl_xor_sync(0xffffffffu, ps, 1);
            ps += __shfl_xor_sync(0xffffffffu, ps, 2);
            pd += __shfl_xor_sync(0xffffffffu, pd, 1);
            pd += __shfl_xor_sync(0xffffffffu, pd, 2);
            if (t == 0 && row < NN) {
                g_ssrc[row * NH + wn * 2 + hl] = ps;
                g_sdst[row * NH + wn * 2 + hl] = pd;
            }
        }
    }
}

// ---------------------------------------------------------------------------
// Scan: per-block inclusive (coalesced) + redundant block-sum apply
// ---------------------------------------------------------------------------
__global__ void scan1_kernel() {
    __shared__ int sh[256];
    int t = threadIdx.x;
    int i = blockIdx.x * 256 + t;
    int v = (i < NN) ? g_cnt[i] : 0;
    sh[t] = v;
    __syncthreads();
    #pragma unroll
    for (int ofs = 1; ofs < 256; ofs <<= 1) {
        int add = (t >= ofs) ? sh[t - ofs] : 0;
        __syncthreads();
        sh[t] += add;
        __syncthreads();
    }
    if (i < NN) g_scan[i] = sh[t];
    if (t == 255) g_bsum[blockIdx.x] = sh[255];
}

__global__ void scan_apply_kernel() {
    __shared__ int sh[256];
    int t = threadIdx.x;
    sh[t] = (t < NB) ? g_bsum[t] : 0;
    __syncthreads();
    #pragma unroll
    for (int ofs = 1; ofs < 256; ofs <<= 1) {
        int add = (t >= ofs) ? sh[t - ofs] : 0;
        __syncthreads();
        sh[t] += add;
        __syncthreads();
    }
    int base = (blockIdx.x == 0) ? 0 : sh[blockIdx.x - 1];
    int i = blockIdx.x * 256 + t;
    if (i < NN) g_off[i] = g_scan[i] - g_cnt[i] + base;
    if (i == 0) g_off[NN] = NE;
}

// Atomic-free fill, 8 edges/thread.
__global__ void fill_kernel(const int* __restrict__ ei) {
    int b = (blockIdx.x * blockDim.x + threadIdx.x) * 8;
    if (b >= NE) return;
    int n = (NE - b < 8) ? (NE - b) : 8;
    int s[8], d[8], lp[8];
    #pragma unroll
    for (int j = 0; j < 8; j++) {
        if (j < n) {
            s[j]  = ei[b + j];
            d[j]  = ei[NE + b + j];
            lp[j] = g_lpos[b + j];
        }
    }
    #pragma unroll
    for (int j = 0; j < 8; j++)
        if (j < n) g_esrc[g_off[d[j]] + lp[j]] = s[j];
}

// ---------------------------------------------------------------------------
// Aggregation (exact round-12 version): warp per dst node, two-pass, smem
// numerator cache, warp-uniform fast/slow branch. Re-zeroes g_cnt.
// ---------------------------------------------------------------------------
#define CAP 64

__device__ __forceinline__ float lrelu_exp(float v) {
    float r = v > 0.f ? v : 0.2f * v;
    return __expf(r);
}

__global__ __launch_bounds__(256)
void agg_kernel(float* __restrict__ out) {
    __shared__ float s_al[8][CAP][NH];   // 8 KB per block

    // re-zero count array for the next replay (all consumers done)
    int gid = blockIdx.x * blockDim.x + threadIdx.x;
    if (gid < NN) g_cnt[gid] = 0;

    int w = threadIdx.x >> 5;
    int d = blockIdx.x * 8 + w;
    if (d >= NN) return;
    int lane = threadIdx.x & 31;
    int beg = g_off[d];
    int deg = g_off[d + 1] - beg;

    float4 sd4 = *(const float4*)&g_sdst[d * 4];

    // Pass 1: per-edge numerators -> smem + denom reduction
    float4 dn = make_float4(0.f, 0.f, 0.f, 0.f);
    for (int j = lane; j < deg; j += 32) {
        int s = g_esrc[beg + j];
        float4 a = *(const float4*)&g_ssrc[s * 4];
        float4 e;
        e.x = lrelu_exp(a.x + sd4.x);
        e.y = lrelu_exp(a.y + sd4.y);
        e.z = lrelu_exp(a.z + sd4.z);
        e.w = lrelu_exp(a.w + sd4.w);
        dn.x += e.x; dn.y += e.y; dn.z += e.z; dn.w += e.w;
        if (j < CAP) *(float4*)&s_al[w][j][0] = e;
    }
    #pragma unroll
    for (int m = 16; m; m >>= 1) {
        dn.x += __shfl_xor_sync(0xffffffffu, dn.x, m);
        dn.y += __shfl_xor_sync(0xffffffffu, dn.y, m);
        dn.z += __shfl_xor_sync(0xffffffffu, dn.z, m);
        dn.w += __shfl_xor_sync(0xffffffffu, dn.w, m);
    }
    __syncwarp();

    int h = lane >> 3;
    float dnh = (h == 0) ? dn.x : (h == 1) ? dn.y : (h == 2) ? dn.z : dn.w;
    float adh = (h == 0) ? sd4.x : (h == 1) ? sd4.y : (h == 2) ? sd4.z : sd4.w;
    float invd = __fdividef(1.f, dnh + 1e-8f);

    // Pass 2: weighted fp16 gather
    float4 acc = make_float4(0.f, 0.f, 0.f, 0.f);
    if (deg <= CAP) {
        const float* al_base = &s_al[w][0][h];
        #pragma unroll 4
        for (int j = 0; j < deg; j++) {
            float al = al_base[j * NH] * invd;
            int s = g_esrc[beg + j];
            float2 raw = *(const float2*)&g_Wx_h[s * MOUT + lane * 4];
            __half2 h01 = ((__half2*)&raw)[0];
            __half2 h23 = ((__half2*)&raw)[1];
            float2 f01 = __half22float2(h01);
            float2 f23 = __half22float2(h23);
            acc.x += al * f01.x; acc.y += al * f01.y;
            acc.z += al * f23.x; acc.w += al * f23.y;
        }
    } else {
        #pragma unroll 2
        for (int j = 0; j < deg; j++) {
            int s = g_esrc[beg + j];
            float al = lrelu_exp(g_ssrc[s * 4 + h] + adh) * invd;
            float2 raw = *(const float2*)&g_Wx_h[s * MOUT + lane * 4];
            __half2 h01 = ((__half2*)&raw)[0];
            __half2 h23 = ((__half2*)&raw)[1];
            float2 f01 = __half22float2(h01);
            float2 f23 = __half22float2(h23);
            acc.x += al * f01.x; acc.y += al * f01.y;
            acc.z += al * f23.x; acc.w += al * f23.y;
        }
    }

    acc.x = acc.x > 0.f ? acc.x : expm1f(acc.x);
    acc.y = acc.y > 0.f ? acc.y : expm1f(acc.y);
    acc.z = acc.z > 0.f ? acc.z : expm1f(acc.z);
    acc.w = acc.w > 0.f ? acc.w : expm1f(acc.w);
    *(float4*)&out[d * MOUT + lane * 4] = acc;
}

// ---------------------------------------------------------------------------
extern "C" void kernel_launch(void* const* d_in, const int* in_sizes, int n_in,
                              void* d_out, int out_size) {
    const float* x  = (const float*)d_in[0];
    const int*   ei = (const int*)d_in[1];
    const float* W  = (const float*)d_in[2];
    const float* aw = (const float*)d_in[3];
    float* out = (float*)d_out;

    gemm_hist_kernel<<<GEMM_BLOCKS + HIST_BLOCKS, 256>>>(x, W, aw, ei);
    scan1_kernel<<<NB, 256>>>();
    scan_apply_kernel<<<NB, 256>>>();
    fill_kernel<<<(NE / 8 + 255) / 256, 256>>>(ei);
    agg_kernel<<<(NN + 7) / 8, 256>>>(out);
}

// round 16
// speedup vs baseline: 1.8297x; 1.0123x over previous
#include <cuda_runtime.h>
#include <cuda_fp16.h>

#define NN   50000
#define NE   800000
#define KIN  256
#define MOUT 128
#define NH   4
#define NB   196        // ceil(NN/256)

#define BMT 128
#define BKT 32
#define XPADH 40        // row stride in halves (80B): conflict-free fragments
#define GEMM_BLOCKS ((NN + BMT - 1) / BMT)      // 391
#define HIST_BLOCKS ((NE + 1023) / 1024)        // 782

// Scratch (allocation-free rule: __device__ globals)
__device__ __align__(16) __half g_Wx_h[NN * MOUT];  // 12.8 MB fp16 Wx for agg
__device__ __align__(16) float g_ssrc[NN * NH];
__device__ __align__(16) float g_sdst[NN * NH];
__device__ int g_cnt[NN];     // zero-init at load; re-zeroed by agg each replay
__device__ int g_bflag[NB];   // scan publish flags (total+1); reset by fill
__device__ int g_off[NN + 1];
__device__ int g_lpos[NE];    // per-edge position within its dst segment
__device__ int g_esrc[NE];

// ---------------------------------------------------------------------------
// Fused GEMM + histogram kernel. GEMM: fp16 mma.m16n8k16 (fp32 accum).
// Blocks [0, GEMM_BLOCKS): GEMM Wx = x@W^T + fused score epilogue.
// Blocks [GEMM_BLOCKS, +HIST_BLOCKS): per-dst histogram recording lpos.
// ---------------------------------------------------------------------------
__device__ __forceinline__ void mma_fp16(float* c, const unsigned* a,
                                         unsigned b0, unsigned b1) {
    asm volatile(
        "mma.sync.aligned.m16n8k16.row.col.f32.f16.f16.f32 "
        "{%0,%1,%2,%3}, {%4,%5,%6,%7}, {%8,%9}, {%0,%1,%2,%3};"
        : "+f"(c[0]), "+f"(c[1]), "+f"(c[2]), "+f"(c[3])
        : "r"(a[0]), "r"(a[1]), "r"(a[2]), "r"(a[3]), "r"(b0), "r"(b1));
}

__global__ __launch_bounds__(256, 2)
void gemm_hist_kernel(const float* __restrict__ x,
                      const float* __restrict__ W,
                      const float* __restrict__ aw,
                      const int* __restrict__ ei) {
    __shared__ __half Xs[BMT * XPADH];   // 10 KB
    __shared__ __half Ws[MOUT * XPADH];  // 10 KB

    if (blockIdx.x >= GEMM_BLOCKS) {
        // ---- histogram branch: count + record local position ----
        int base = (blockIdx.x - GEMM_BLOCKS) * 1024 + threadIdx.x;
        #pragma unroll
        for (int j = 0; j < 4; j++) {
            int e = base + j * 256;
            if (e < NE) {
                int d = ei[NE + e];
                int lp = atomicAdd(&g_cnt[d], 1);
                g_lpos[e] = lp;
            }
        }
        return;
    }

    // ---- GEMM branch ----
    int tid  = threadIdx.x;
    int lane = tid & 31;
    int warp = tid >> 5;
    int g = lane >> 2;
    int t = lane & 3;
    int wm = warp & 3;
    int wn = warp >> 2;
    int row0 = blockIdx.x * BMT;

    float c[2][8][4];
    #pragma unroll
    for (int tm = 0; tm < 2; tm++)
        #pragma unroll
        for (int tn = 0; tn < 8; tn++)
            #pragma unroll
            for (int i = 0; i < 4; i++) c[tm][tn][i] = 0.f;

    for (int k0 = 0; k0 < KIN; k0 += BKT) {
        #pragma unroll
        for (int j = 0; j < 4; j++) {
            int idx = tid + 256 * j;
            int m   = idx >> 3;
            int kv  = (idx & 7) * 4;
            int row = row0 + m;
            float4 v = make_float4(0.f, 0.f, 0.f, 0.f);
            if (row < NN) v = *(const float4*)&x[row * KIN + k0 + kv];
            __half2 hx0 = __floats2half2_rn(v.x, v.y);
            __half2 hx1 = __floats2half2_rn(v.z, v.w);
            uint2 ux = make_uint2(*(unsigned*)&hx0, *(unsigned*)&hx1);
            *(uint2*)&Xs[m * XPADH + kv] = ux;

            float4 w4 = *(const float4*)&W[m * KIN + k0 + kv];
            __half2 hw0 = __floats2half2_rn(w4.x, w4.y);
            __half2 hw1 = __floats2half2_rn(w4.z, w4.w);
            uint2 uw = make_uint2(*(unsigned*)&hw0, *(unsigned*)&hw1);
            *(uint2*)&Ws[m * XPADH + kv] = uw;
        }
        __syncthreads();

        #pragma unroll
        for (int kk = 0; kk < BKT; kk += 16) {
            unsigned a[2][4];
            #pragma unroll
            for (int tm = 0; tm < 2; tm++) {
                int r = wm * 32 + tm * 16 + g;
                a[tm][0] = *(unsigned*)&Xs[r * XPADH + kk + 2 * t];
                a[tm][1] = *(unsigned*)&Xs[(r + 8) * XPADH + kk + 2 * t];
                a[tm][2] = *(unsigned*)&Xs[r * XPADH + kk + 2 * t + 8];
                a[tm][3] = *(unsigned*)&Xs[(r + 8) * XPADH + kk + 2 * t + 8];
            }
            #pragma unroll
            for (int tn = 0; tn < 8; tn++) {
                int n = wn * 64 + tn * 8 + g;
                unsigned b0 = *(unsigned*)&Ws[n * XPADH + kk + 2 * t];
                unsigned b1 = *(unsigned*)&Ws[n * XPADH + kk + 2 * t + 8];
                mma_fp16(c[0][tn], a[0], b0, b1);
                mma_fp16(c[1][tn], a[1], b0, b1);
            }
        }
        __syncthreads();
    }

    float as_r[4][2], ad_r[4][2];
    #pragma unroll
    for (int q = 0; q < 4; q++)
        #pragma unroll
        for (int j = 0; j < 2; j++) {
            as_r[q][j] = aw[q * 8 + 2 * t + j];
            ad_r[q][j] = aw[32 + q * 8 + 2 * t + j];
        }

    #pragma unroll
    for (int tm = 0; tm < 2; tm++)
    #pragma unroll
    for (int half = 0; half < 2; half++) {
        int row = row0 + wm * 32 + tm * 16 + half * 8 + g;

        if (row < NN) {
            #pragma unroll
            for (int tn = 0; tn < 8; tn++) {
                __half2 hv = __floats2half2_rn(c[tm][tn][half * 2],
                                               c[tm][tn][half * 2 + 1]);
                *(__half2*)&g_Wx_h[row * MOUT + wn * 64 + tn * 8 + 2 * t] = hv;
            }
        }

        #pragma unroll
        for (int hl = 0; hl < 2; hl++) {
            float ps = 0.f, pd = 0.f;
            #pragma unroll
            for (int q = 0; q < 4; q++)
                #pragma unroll
                for (int j = 0; j < 2; j++) {
                    float v = c[tm][hl * 4 + q][half * 2 + j];
                    ps += v * as_r[q][j];
                    pd += v * ad_r[q][j];
                }
            ps += __shfl_xor_sync(0xffffffffu, ps, 1);
            ps += __shfl_xor_sync(0xffffffffu, ps, 2);
            pd += __shfl_xor_sync(0xffffffffu, pd, 1);
            pd += __shfl_xor_sync(0xffffffffu, pd, 2);
            if (t == 0 && row < NN) {
                g_ssrc[row * NH + wn * 2 + hl] = ps;
                g_sdst[row * NH + wn * 2 + hl] = pd;
            }
        }
    }
}

// ---------------------------------------------------------------------------
// Single-pass scan: local inclusive scan, publish block total via atomic
// (value = total+1, so 0 means "not yet"), spin-read all block totals,
// scan them in smem, write final exclusive offsets. Flags reset by fill.
// ---------------------------------------------------------------------------
__global__ void scan_kernel() {
    __shared__ int sh[256];
    __shared__ int bs[256];
    int t = threadIdx.x;
    int i = blockIdx.x * 256 + t;
    int v = (i < NN) ? g_cnt[i] : 0;
    sh[t] = v;
    __syncthreads();
    #pragma unroll
    for (int ofs = 1; ofs < 256; ofs <<= 1) {
        int add = (t >= ofs) ? sh[t - ofs] : 0;
        __syncthreads();
        sh[t] += add;
        __syncthreads();
    }

    // publish this block's total (value+1 rides in the atomic)
    if (t == 0) atomicExch(&g_bflag[blockIdx.x], sh[255] + 1);

    // spin-read all block totals (all 196 blocks are co-resident on 148 SMs)
    if (t < NB) {
        int f;
        do { f = atomicAdd(&g_bflag[t], 0); } while (f == 0);
        bs[t] = f - 1;
    } else {
        bs[t] = 0;
    }
    __syncthreads();
    #pragma unroll
    for (int ofs = 1; ofs < 256; ofs <<= 1) {
        int add = (t >= ofs) ? bs[t - ofs] : 0;
        __syncthreads();
        bs[t] += add;
        __syncthreads();
    }

    int base = (blockIdx.x == 0) ? 0 : bs[blockIdx.x - 1];
    if (i < NN) g_off[i] = sh[t] - v + base;
    if (i == 0) g_off[NN] = NE;
}

// Atomic-free fill, 2 edges/thread (grid 1563 for TLP). Also resets scan flags.
__global__ void fill_kernel(const int* __restrict__ ei) {
    int gid = blockIdx.x * blockDim.x + threadIdx.x;
    if (gid < NB) g_bflag[gid] = 0;      // reset for next replay (scan is done)
    int b = gid * 2;
    if (b >= NE) return;
    int s0 = ei[b];
    int d0 = ei[NE + b];
    int l0 = g_lpos[b];
    bool two = (b + 1 < NE);
    int s1 = 0, d1 = 0, l1 = 0;
    if (two) {
        s1 = ei[b + 1];
        d1 = ei[NE + b + 1];
        l1 = g_lpos[b + 1];
    }
    g_esrc[g_off[d0] + l0] = s0;
    if (two) g_esrc[g_off[d1] + l1] = s1;
}

// ---------------------------------------------------------------------------
// Aggregation (exact round-12 version): warp per dst node, two-pass, smem
// numerator cache, warp-uniform fast/slow branch. Re-zeroes g_cnt.
// ---------------------------------------------------------------------------
#define CAP 64

__device__ __forceinline__ float lrelu_exp(float v) {
    float r = v > 0.f ? v : 0.2f * v;
    return __expf(r);
}

__global__ __launch_bounds__(256)
void agg_kernel(float* __restrict__ out) {
    __shared__ float s_al[8][CAP][NH];   // 8 KB per block

    // re-zero count array for the next replay (all consumers done)
    int gid = blockIdx.x * blockDim.x + threadIdx.x;
    if (gid < NN) g_cnt[gid] = 0;

    int w = threadIdx.x >> 5;
    int d = blockIdx.x * 8 + w;
    if (d >= NN) return;
    int lane = threadIdx.x & 31;
    int beg = g_off[d];
    int deg = g_off[d + 1] - beg;

    float4 sd4 = *(const float4*)&g_sdst[d * 4];

    // Pass 1: per-edge numerators -> smem + denom reduction
    float4 dn = make_float4(0.f, 0.f, 0.f, 0.f);
    for (int j = lane; j < deg; j += 32) {
        int s = g_esrc[beg + j];
        float4 a = *(const float4*)&g_ssrc[s * 4];
        float4 e;
        e.x = lrelu_exp(a.x + sd4.x);
        e.y = lrelu_exp(a.y + sd4.y);
        e.z = lrelu_exp(a.z + sd4.z);
        e.w = lrelu_exp(a.w + sd4.w);
        dn.x += e.x; dn.y += e.y; dn.z += e.z; dn.w += e.w;
        if (j < CAP) *(float4*)&s_al[w][j][0] = e;
    }
    #pragma unroll
    for (int m = 16; m; m >>= 1) {
        dn.x += __shfl_xor_sync(0xffffffffu, dn.x, m);
        dn.y += __shfl_xor_sync(0xffffffffu, dn.y, m);
        dn.z += __shfl_xor_sync(0xffffffffu, dn.z, m);
        dn.w += __shfl_xor_sync(0xffffffffu, dn.w, m);
    }
    __syncwarp();

    int h = lane >> 3;
    float dnh = (h == 0) ? dn.x : (h == 1) ? dn.y : (h == 2) ? dn.z : dn.w;
    float adh = (h == 0) ? sd4.x : (h == 1) ? sd4.y : (h == 2) ? sd4.z : sd4.w;
    float invd = __fdividef(1.f, dnh + 1e-8f);

    // Pass 2: weighted fp16 gather
    float4 acc = make_float4(0.f, 0.f, 0.f, 0.f);
    if (deg <= CAP) {
        const float* al_base = &s_al[w][0][h];
        #pragma unroll 4
        for (int j = 0; j < deg; j++) {
            float al = al_base[j * NH] * invd;
            int s = g_esrc[beg + j];
            float2 raw = *(const float2*)&g_Wx_h[s * MOUT + lane * 4];
            __half2 h01 = ((__half2*)&raw)[0];
            __half2 h23 = ((__half2*)&raw)[1];
            float2 f01 = __half22float2(h01);
            float2 f23 = __half22float2(h23);
            acc.x += al * f01.x; acc.y += al * f01.y;
            acc.z += al * f23.x; acc.w += al * f23.y;
        }
    } else {
        #pragma unroll 2
        for (int j = 0; j < deg; j++) {
            int s = g_esrc[beg + j];
            float al = lrelu_exp(g_ssrc[s * 4 + h] + adh) * invd;
            float2 raw = *(const float2*)&g_Wx_h[s * MOUT + lane * 4];
            __half2 h01 = ((__half2*)&raw)[0];
            __half2 h23 = ((__half2*)&raw)[1];
            float2 f01 = __half22float2(h01);
            float2 f23 = __half22float2(h23);
            acc.x += al * f01.x; acc.y += al * f01.y;
            acc.z += al * f23.x; acc.w += al * f23.y;
        }
    }

    acc.x = acc.x > 0.f ? acc.x : expm1f(acc.x);
    acc.y = acc.y > 0.f ? acc.y : expm1f(acc.y);
    acc.z = acc.z > 0.f ? acc.z : expm1f(acc.z);
    acc.w = acc.w > 0.f ? acc.w : expm1f(acc.w);
    *(float4*)&out[d * MOUT + lane * 4] = acc;
}

// ---------------------------------------------------------------------------
extern "C" void kernel_launch(void* const* d_in, const int* in_sizes, int n_in,
                              void* d_out, int out_size) {
    const float* x  = (const float*)d_in[0];
    const int*   ei = (const int*)d_in[1];
    const float* W  = (const float*)d_in[2];
    const float* aw = (const float*)d_in[3];
    float* out = (float*)d_out;

    gemm_hist_kernel<<<GEMM_BLOCKS + HIST_BLOCKS, 256>>>(x, W, aw, ei);
    scan_kernel<<<NB, 256>>>();
    fill_kernel<<<(NE / 2 + 255) / 256, 256>>>(ei);
    agg_kernel<<<(NN + 7) / 8, 256>>>(out);
}

// round 17
// speedup vs baseline: 1.9805x; 1.0824x over previous
#include <cuda_runtime.h>
#include <cuda_fp16.h>

#define NN   50000
#define NE   800000
#define KIN  256
#define MOUT 128
#define NH   4
#define NB   196        // ceil(NN/256)

#define BMT 128
#define BKT 32
#define XPADH 40        // row stride in halves (80B): conflict-free fragments
#define GEMM_BLOCKS ((NN + BMT - 1) / BMT)      // 391
#define HIST_BLOCKS ((NE + 1023) / 1024)        // 782

// Scratch (allocation-free rule: __device__ globals)
__device__ __align__(16) __half g_Wx_h[NN * MOUT];  // 12.8 MB fp16 Wx for agg
__device__ __align__(16) float g_ssrc[NN * NH];
__device__ __align__(16) float g_sdst[NN * NH];
__device__ int g_cnt[NN];     // zero-init at load; re-zeroed by agg each replay
__device__ int g_bflag[NB];   // scan publish flags (total+1); reset by fill
__device__ int g_off[NN + 1];
__device__ int g_lpos[NE];    // per-edge position within its dst segment
__device__ int g_esrc[NE];

// ---------------------------------------------------------------------------
// Fused GEMM + histogram kernel. GEMM: fp16 mma.m16n8k16 (fp32 accum).
// ---------------------------------------------------------------------------
__device__ __forceinline__ void mma_fp16(float* c, const unsigned* a,
                                         unsigned b0, unsigned b1) {
    asm volatile(
        "mma.sync.aligned.m16n8k16.row.col.f32.f16.f16.f32 "
        "{%0,%1,%2,%3}, {%4,%5,%6,%7}, {%8,%9}, {%0,%1,%2,%3};"
        : "+f"(c[0]), "+f"(c[1]), "+f"(c[2]), "+f"(c[3])
        : "r"(a[0]), "r"(a[1]), "r"(a[2]), "r"(a[3]), "r"(b0), "r"(b1));
}

__global__ __launch_bounds__(256, 2)
void gemm_hist_kernel(const float* __restrict__ x,
                      const float* __restrict__ W,
                      const float* __restrict__ aw,
                      const int* __restrict__ ei) {
    __shared__ __half Xs[BMT * XPADH];   // 10 KB
    __shared__ __half Ws[MOUT * XPADH];  // 10 KB

    if (blockIdx.x >= GEMM_BLOCKS) {
        // ---- histogram branch: count + record local position ----
        int base = (blockIdx.x - GEMM_BLOCKS) * 1024 + threadIdx.x;
        #pragma unroll
        for (int j = 0; j < 4; j++) {
            int e = base + j * 256;
            if (e < NE) {
                int d = ei[NE + e];
                int lp = atomicAdd(&g_cnt[d], 1);
                g_lpos[e] = lp;
            }
        }
        return;
    }

    // ---- GEMM branch ----
    int tid  = threadIdx.x;
    int lane = tid & 31;
    int warp = tid >> 5;
    int g = lane >> 2;
    int t = lane & 3;
    int wm = warp & 3;
    int wn = warp >> 2;
    int row0 = blockIdx.x * BMT;

    float c[2][8][4];
    #pragma unroll
    for (int tm = 0; tm < 2; tm++)
        #pragma unroll
        for (int tn = 0; tn < 8; tn++)
            #pragma unroll
            for (int i = 0; i < 4; i++) c[tm][tn][i] = 0.f;

    for (int k0 = 0; k0 < KIN; k0 += BKT) {
        #pragma unroll
        for (int j = 0; j < 4; j++) {
            int idx = tid + 256 * j;
            int m   = idx >> 3;
            int kv  = (idx & 7) * 4;
            int row = row0 + m;
            float4 v = make_float4(0.f, 0.f, 0.f, 0.f);
            if (row < NN) v = *(const float4*)&x[row * KIN + k0 + kv];
            __half2 hx0 = __floats2half2_rn(v.x, v.y);
            __half2 hx1 = __floats2half2_rn(v.z, v.w);
            uint2 ux = make_uint2(*(unsigned*)&hx0, *(unsigned*)&hx1);
            *(uint2*)&Xs[m * XPADH + kv] = ux;

            float4 w4 = *(const float4*)&W[m * KIN + k0 + kv];
            __half2 hw0 = __floats2half2_rn(w4.x, w4.y);
            __half2 hw1 = __floats2half2_rn(w4.z, w4.w);
            uint2 uw = make_uint2(*(unsigned*)&hw0, *(unsigned*)&hw1);
            *(uint2*)&Ws[m * XPADH + kv] = uw;
        }
        __syncthreads();

        #pragma unroll
        for (int kk = 0; kk < BKT; kk += 16) {
            unsigned a[2][4];
            #pragma unroll
            for (int tm = 0; tm < 2; tm++) {
                int r = wm * 32 + tm * 16 + g;
                a[tm][0] = *(unsigned*)&Xs[r * XPADH + kk + 2 * t];
                a[tm][1] = *(unsigned*)&Xs[(r + 8) * XPADH + kk + 2 * t];
                a[tm][2] = *(unsigned*)&Xs[r * XPADH + kk + 2 * t + 8];
                a[tm][3] = *(unsigned*)&Xs[(r + 8) * XPADH + kk + 2 * t + 8];
            }
            #pragma unroll
            for (int tn = 0; tn < 8; tn++) {
                int n = wn * 64 + tn * 8 + g;
                unsigned b0 = *(unsigned*)&Ws[n * XPADH + kk + 2 * t];
                unsigned b1 = *(unsigned*)&Ws[n * XPADH + kk + 2 * t + 8];
                mma_fp16(c[0][tn], a[0], b0, b1);
                mma_fp16(c[1][tn], a[1], b0, b1);
            }
        }
        __syncthreads();
    }

    float as_r[4][2], ad_r[4][2];
    #pragma unroll
    for (int q = 0; q < 4; q++)
        #pragma unroll
        for (int j = 0; j < 2; j++) {
            as_r[q][j] = aw[q * 8 + 2 * t + j];
            ad_r[q][j] = aw[32 + q * 8 + 2 * t + j];
        }

    #pragma unroll
    for (int tm = 0; tm < 2; tm++)
    #pragma unroll
    for (int half = 0; half < 2; half++) {
        int row = row0 + wm * 32 + tm * 16 + half * 8 + g;

        if (row < NN) {
            #pragma unroll
            for (int tn = 0; tn < 8; tn++) {
                __half2 hv = __floats2half2_rn(c[tm][tn][half * 2],
                                               c[tm][tn][half * 2 + 1]);
                *(__half2*)&g_Wx_h[row * MOUT + wn * 64 + tn * 8 + 2 * t] = hv;
            }
        }

        #pragma unroll
        for (int hl = 0; hl < 2; hl++) {
            float ps = 0.f, pd = 0.f;
            #pragma unroll
            for (int q = 0; q < 4; q++)
                #pragma unroll
                for (int j = 0; j < 2; j++) {
                    float v = c[tm][hl * 4 + q][half * 2 + j];
                    ps += v * as_r[q][j];
                    pd += v * ad_r[q][j];
                }
            ps += __shfl_xor_sync(0xffffffffu, ps, 1);
            ps += __shfl_xor_sync(0xffffffffu, ps, 2);
            pd += __shfl_xor_sync(0xffffffffu, pd, 1);
            pd += __shfl_xor_sync(0xffffffffu, pd, 2);
            if (t == 0 && row < NN) {
                g_ssrc[row * NH + wn * 2 + hl] = ps;
                g_sdst[row * NH + wn * 2 + hl] = pd;
            }
        }
    }
}

// ---------------------------------------------------------------------------
// Single-pass scan (publish block totals via atomics, spin, apply).
// ---------------------------------------------------------------------------
__global__ void scan_kernel() {
    __shared__ int sh[256];
    __shared__ int bs[256];
    int t = threadIdx.x;
    int i = blockIdx.x * 256 + t;
    int v = (i < NN) ? g_cnt[i] : 0;
    sh[t] = v;
    __syncthreads();
    #pragma unroll
    for (int ofs = 1; ofs < 256; ofs <<= 1) {
        int add = (t >= ofs) ? sh[t - ofs] : 0;
        __syncthreads();
        sh[t] += add;
        __syncthreads();
    }

    if (t == 0) atomicExch(&g_bflag[blockIdx.x], sh[255] + 1);

    if (t < NB) {
        int f;
        do { f = atomicAdd(&g_bflag[t], 0); } while (f == 0);
        bs[t] = f - 1;
    } else {
        bs[t] = 0;
    }
    __syncthreads();
    #pragma unroll
    for (int ofs = 1; ofs < 256; ofs <<= 1) {
        int add = (t >= ofs) ? bs[t - ofs] : 0;
        __syncthreads();
        bs[t] += add;
        __syncthreads();
    }

    int base = (blockIdx.x == 0) ? 0 : bs[blockIdx.x - 1];
    if (i < NN) g_off[i] = sh[t] - v + base;
    if (i == 0) g_off[NN] = NE;
}

// Atomic-free fill, 2 edges/thread. Also resets scan flags.
__global__ void fill_kernel(const int* __restrict__ ei) {
    int gid = blockIdx.x * blockDim.x + threadIdx.x;
    if (gid < NB) g_bflag[gid] = 0;
    int b = gid * 2;
    if (b >= NE) return;
    int s0 = ei[b];
    int d0 = ei[NE + b];
    int l0 = g_lpos[b];
    bool two = (b + 1 < NE);
    int s1 = 0, d1 = 0, l1 = 0;
    if (two) {
        s1 = ei[b + 1];
        d1 = ei[NE + b + 1];
        l1 = g_lpos[b + 1];
    }
    g_esrc[g_off[d0] + l0] = s0;
    if (two) g_esrc[g_off[d1] + l1] = s1;
}

// ---------------------------------------------------------------------------
// Aggregation: warp per dst node, two-pass, smem numerator + src-id cache,
// deferred normalization, cheap ELU (__expf-1). Re-zeroes g_cnt.
// ---------------------------------------------------------------------------
#define CAP 64

__device__ __forceinline__ float lrelu_exp(float v) {
    float r = v > 0.f ? v : 0.2f * v;
    return __expf(r);
}

__device__ __forceinline__ float elu(float v) {
    return v > 0.f ? v : (__expf(v) - 1.f);
}

__global__ __launch_bounds__(256)
void agg_kernel(float* __restrict__ out) {
    __shared__ float s_al[8][CAP][NH];   // 8 KB
    __shared__ int   s_src[8][CAP];      // 2 KB

    // re-zero count array for the next replay (all consumers done)
    int gid = blockIdx.x * blockDim.x + threadIdx.x;
    if (gid < NN) g_cnt[gid] = 0;

    int w = threadIdx.x >> 5;
    int d = blockIdx.x * 8 + w;
    if (d >= NN) return;
    int lane = threadIdx.x & 31;
    int beg = g_off[d];
    int deg = g_off[d + 1] - beg;

    float4 sd4 = *(const float4*)&g_sdst[d * 4];

    // Pass 1: per-edge numerators + src ids -> smem, denom reduction
    float4 dn = make_float4(0.f, 0.f, 0.f, 0.f);
    for (int j = lane; j < deg; j += 32) {
        int s = g_esrc[beg + j];
        float4 a = *(const float4*)&g_ssrc[s * 4];
        float4 e;
        e.x = lrelu_exp(a.x + sd4.x);
        e.y = lrelu_exp(a.y + sd4.y);
        e.z = lrelu_exp(a.z + sd4.z);
        e.w = lrelu_exp(a.w + sd4.w);
        dn.x += e.x; dn.y += e.y; dn.z += e.z; dn.w += e.w;
        if (j < CAP) {
            *(float4*)&s_al[w][j][0] = e;
            s_src[w][j] = s;
        }
    }
    #pragma unroll
    for (int m = 16; m; m >>= 1) {
        dn.x += __shfl_xor_sync(0xffffffffu, dn.x, m);
        dn.y += __shfl_xor_sync(0xffffffffu, dn.y, m);
        dn.z += __shfl_xor_sync(0xffffffffu, dn.z, m);
        dn.w += __shfl_xor_sync(0xffffffffu, dn.w, m);
    }
    __syncwarp();

    int h = lane >> 3;
    float dnh = (h == 0) ? dn.x : (h == 1) ? dn.y : (h == 2) ? dn.z : dn.w;
    float adh = (h == 0) ? sd4.x : (h == 1) ? sd4.y : (h == 2) ? sd4.z : sd4.w;
    float invd = __fdividef(1.f, dnh + 1e-8f);

    // Pass 2: un-normalized weighted fp16 gather; scale once at the end.
    float4 acc = make_float4(0.f, 0.f, 0.f, 0.f);
    if (deg <= CAP) {
        const float* al_base = &s_al[w][0][h];
        #pragma unroll 4
        for (int j = 0; j < deg; j++) {
            float e = al_base[j * NH];            // LDS (8-lane broadcast)
            int s = s_src[w][j];                  // LDS (warp broadcast)
            float2 raw = *(const float2*)&g_Wx_h[s * MOUT + lane * 4];
            __half2 h01 = ((__half2*)&raw)[0];
            __half2 h23 = ((__half2*)&raw)[1];
            float2 f01 = __half22float2(h01);
            float2 f23 = __half22float2(h23);
            acc.x += e * f01.x; acc.y += e * f01.y;
            acc.z += e * f23.x; acc.w += e * f23.y;
        }
    } else {
        #pragma unroll 2
        for (int j = 0; j < deg; j++) {
            int s = g_esrc[beg + j];
            float e = lrelu_exp(g_ssrc[s * 4 + h] + adh);
            float2 raw = *(const float2*)&g_Wx_h[s * MOUT + lane * 4];
            __half2 h01 = ((__half2*)&raw)[0];
            __half2 h23 = ((__half2*)&raw)[1];
            float2 f01 = __half22float2(h01);
            float2 f23 = __half22float2(h23);
            acc.x += e * f01.x; acc.y += e * f01.y;
            acc.z += e * f23.x; acc.w += e * f23.y;
        }
    }

    acc.x = elu(acc.x * invd);
    acc.y = elu(acc.y * invd);
    acc.z = elu(acc.z * invd);
    acc.w = elu(acc.w * invd);
    *(float4*)&out[d * MOUT + lane * 4] = acc;
}

// ---------------------------------------------------------------------------
extern "C" void kernel_launch(void* const* d_in, const int* in_sizes, int n_in,
                              void* d_out, int out_size) {
    const float* x  = (const float*)d_in[0];
    const int*   ei = (const int*)d_in[1];
    const float* W  = (const float*)d_in[2];
    const float* aw = (const float*)d_in[3];
    float* out = (float*)d_out;

    gemm_hist_kernel<<<GEMM_BLOCKS + HIST_BLOCKS, 256>>>(x, W, aw, ei);
    scan_kernel<<<NB, 256>>>();
    fill_kernel<<<(NE / 2 + 255) / 256, 256>>>(ei);
    agg_kernel<<<(NN + 7) / 8, 256>>>(out);
}